// round 3
// baseline (speedup 1.0000x reference)
#include <cuda_runtime.h>

// involution: out[b, g*64+c, h, w] = sum_{kh,kw} x[b, g*64+c, h+kh-3, w+kw-3] * wt[b,g,kh,kw,h,w]
// B=8, G=8, CPG=64, H=W=64, K=7, pad=3, stride=1.

#define NTHREADS 128
#define TH 4
#define ROWS 10            // TH + 6
#define SMW 72             // padded row stride (floats), smem col s <-> global col s-3
#define TILE_ELEMS 700     // ROWS * 70
#define BUF_FLOATS 720     // ROWS * SMW
#define NBUF 8
#define BUF_BYTES (BUF_FLOATS * 4)

__device__ __forceinline__ unsigned long long pk2(float lo, float hi) {
    unsigned long long r;
    asm("mov.b64 %0, {%1, %2};" : "=l"(r) : "f"(lo), "f"(hi));
    return r;
}
__device__ __forceinline__ unsigned long long ffma2(unsigned long long a,
                                                    unsigned long long b,
                                                    unsigned long long c) {
    unsigned long long d;
    asm("fma.rn.f32x2 %0, %1, %2, %3;" : "=l"(d) : "l"(a), "l"(b), "l"(c));
    return d;
}
__device__ __forceinline__ float f2lo(unsigned long long v) {
    float a, b;
    asm("mov.b64 {%0, %1}, %2;" : "=f"(a), "=f"(b) : "l"(v));
    return a;
}
__device__ __forceinline__ float f2hi(unsigned long long v) {
    float a, b;
    asm("mov.b64 {%0, %1}, %2;" : "=f"(a), "=f"(b) : "l"(v));
    return b;
}
__device__ __forceinline__ void cp_async4(unsigned dst, const void* src) {
    asm volatile("cp.async.ca.shared.global [%0], [%1], 4;" :: "r"(dst), "l"(src));
}
__device__ __forceinline__ void cp_commit() {
    asm volatile("cp.async.commit_group;");
}
__device__ __forceinline__ void cp_wait4() {
    asm volatile("cp.async.wait_group 4;");
}

__global__ void __launch_bounds__(NTHREADS, 4) involution_kernel(
    const float* __restrict__ x, const float* __restrict__ wt, float* __restrict__ out)
{
    __shared__ __align__(16) float sbuf[NBUF * BUF_FLOATS];

    const int tid = threadIdx.x;
    const int bid = blockIdx.x;
    const int ht = bid & 15;         // 16 h-tiles of 4 rows
    const int g  = (bid >> 4) & 7;
    const int b  = bid >> 7;
    const int h0 = ht * TH;
    const int u  = tid & 31;
    const int hy = tid >> 5;         // 0..3
    const int h  = h0 + hy;
    const int w0 = 2 * u;

    unsigned smem_base;
    {
        unsigned long long t;
        asm("cvta.to.shared.u64 %0, %1;" : "=l"(t) : "l"((const void*)sbuf));
        smem_base = (unsigned)t;
    }

    // zero all buffers once (cp.async never writes padding/OOB slots; they must stay 0)
    for (int i = tid; i < NBUF * BUF_FLOATS; i += NTHREADS) sbuf[i] = 0.0f;

    // ---- per-thread weights (98 regs):
    const float* wb = wt + ((b * 8 + g) * 49) * 4096 + h * 64 + w0;
    unsigned long long WE[7][3], WO[7][3];
    float WEs[7], WOs[7];
#pragma unroll
    for (int kh = 0; kh < 7; kh++) {
        float we[7], wo[7];
#pragma unroll
        for (int kw = 0; kw < 7; kw++) {
            float2 p = *(const float2*)(wb + (kh * 7 + kw) * 4096);
            we[kw] = p.x; wo[kw] = p.y;
        }
        WE[kh][0] = pk2(we[0], we[1]);
        WE[kh][1] = pk2(we[2], we[3]);
        WE[kh][2] = pk2(we[4], we[5]);
        WEs[kh]   = we[6];
        WO[kh][0] = pk2(wo[1], wo[2]);
        WO[kh][1] = pk2(wo[3], wo[4]);
        WO[kh][2] = pk2(wo[5], wo[6]);
        WOs[kh]   = wo[0];
    }

    // ---- tile-load slots (invariant over channel loop)
    unsigned sdst[6];
    int goff[6];
    bool ok[6];
#pragma unroll
    for (int k = 0; k < 6; k++) {
        int idx = tid + k * NTHREADS;
        int row = idx / 70;
        int col = idx - row * 70;
        int hh = h0 - 3 + row;
        int ww = col - 3;
        sdst[k] = (unsigned)((row * SMW + col) * 4);
        goff[k] = hh * 64 + ww;
        ok[k] = (idx < TILE_ELEMS) && (hh >= 0) && (hh < 64) && (ww >= 0) && (ww < 64);
    }

    const float* xg = x + ((b * 8 + g) * 64) * 4096;
    float* og = out + ((b * 8 + g) * 64) * 4096 + h * 64 + w0;

    __syncthreads();   // buffers zeroed before any cp.async lands

    // ---- prologue: issue channels 0..3, one commit group each
#pragma unroll
    for (int pre = 0; pre < 4; pre++) {
        unsigned dbase = smem_base + pre * BUF_BYTES;
        const float* xs = xg + pre * 4096;
#pragma unroll
        for (int k = 0; k < 6; k++)
            if (ok[k]) cp_async4(dbase + sdst[k], xs + goff[k]);
        cp_commit();
    }

#pragma unroll 1
    for (int i = 0; i < 32; i++) {
        const int c0 = 2 * i;
        // issue channels c0+4, c0+5 (empty commit groups near the end keep counts consistent)
#pragma unroll
        for (int pre = 0; pre < 2; pre++) {
            int cl = c0 + 4 + pre;
            if (cl < 64) {
                unsigned dbase = smem_base + (cl & 7) * BUF_BYTES;
                const float* xs = xg + cl * 4096;
#pragma unroll
                for (int k = 0; k < 6; k++)
                    if (ok[k]) cp_async4(dbase + sdst[k], xs + goff[k]);
            }
            cp_commit();
        }
        cp_wait4();          // groups for c0, c0+1 complete
        __syncthreads();

        // ---- compute channels c0 and c0+1 back to back (independent chains)
#pragma unroll
        for (int q = 0; q < 2; q++) {
            const int c = c0 + q;
            const float* sb = sbuf + (c & 7) * BUF_FLOATS + hy * SMW + w0;
            unsigned long long ae = 0ULL, ao = 0ULL;
            float se = 0.0f, so = 0.0f;
#pragma unroll
            for (int kh = 0; kh < 7; kh++) {
                const unsigned long long* r = (const unsigned long long*)(sb + kh * SMW);
                unsigned long long P0 = r[0];
                unsigned long long P1 = r[1];
                unsigned long long P2 = r[2];
                unsigned long long P3 = r[3];
                ae = ffma2(P0, WE[kh][0], ae);
                ao = ffma2(P1, WO[kh][0], ao);
                ae = ffma2(P1, WE[kh][1], ae);
                ao = ffma2(P2, WO[kh][1], ao);
                ae = ffma2(P2, WE[kh][2], ae);
                ao = ffma2(P3, WO[kh][2], ao);
                se = fmaf(f2lo(P3), WEs[kh], se);
                so = fmaf(f2hi(P0), WOs[kh], so);
            }
            float eo0 = f2lo(ae) + f2hi(ae) + se;
            float eo1 = f2lo(ao) + f2hi(ao) + so;
            *(float2*)(og + c * 4096) = make_float2(eo0, eo1);
        }
    }
}

extern "C" void kernel_launch(void* const* d_in, const int* in_sizes, int n_in,
                              void* d_out, int out_size) {
    const float* x  = (const float*)d_in[0];
    const float* wt = (const float*)d_in[1];
    if (n_in >= 2 && in_sizes[0] == 8 * 8 * 7 * 7 * 64 * 64) {
        const float* t = x; x = wt; wt = t;
    }
    float* out = (float*)d_out;
    involution_kernel<<<1024, NTHREADS>>>(x, wt, out);
}

// round 4
// speedup vs baseline: 1.3893x; 1.3893x over previous
#include <cuda_runtime.h>

// involution: out[b, g*64+c, h, w] = sum_{kh,kw} x[b, g*64+c, h+kh-3, w+kw-3] * wt[b,g,kh,kw,h,w]
// B=8, G=8, CPG=64, H=W=64, K=7, pad=3, stride=1.
// 2x2 register blocking: each thread computes outputs (ha,wa),(ha,wa+1),(hb,wa),(hb,wa+1), hb=ha+1.

#define NTHREADS 128
#define TH 8
#define ROWS 14            // TH + 6
#define SMW 72             // padded row stride (floats); smem col s <-> global col s-3
#define TILE_ELEMS 980     // ROWS * 70
#define BUF_FLOATS 1008    // ROWS * SMW
#define NBUF 6
#define BUF_BYTES (BUF_FLOATS * 4)

__device__ __forceinline__ unsigned long long pk2(float lo, float hi) {
    unsigned long long r;
    asm("mov.b64 %0, {%1, %2};" : "=l"(r) : "f"(lo), "f"(hi));
    return r;
}
__device__ __forceinline__ unsigned long long ffma2(unsigned long long a,
                                                    unsigned long long b,
                                                    unsigned long long c) {
    unsigned long long d;
    asm("fma.rn.f32x2 %0, %1, %2, %3;" : "=l"(d) : "l"(a), "l"(b), "l"(c));
    return d;
}
__device__ __forceinline__ float f2lo(unsigned long long v) {
    float a, b;
    asm("mov.b64 {%0, %1}, %2;" : "=f"(a), "=f"(b) : "l"(v));
    return a;
}
__device__ __forceinline__ float f2hi(unsigned long long v) {
    float a, b;
    asm("mov.b64 {%0, %1}, %2;" : "=f"(a), "=f"(b) : "l"(v));
    return b;
}
__device__ __forceinline__ void cp_async4(unsigned dst, const void* src) {
    asm volatile("cp.async.ca.shared.global [%0], [%1], 4;" :: "r"(dst), "l"(src));
}
__device__ __forceinline__ void cp_commit() {
    asm volatile("cp.async.commit_group;");
}
__device__ __forceinline__ void cp_wait4() {
    asm volatile("cp.async.wait_group 4;");
}

__global__ void __launch_bounds__(NTHREADS, 2) involution_kernel(
    const float* __restrict__ x, const float* __restrict__ wt, float* __restrict__ out)
{
    __shared__ __align__(16) float sbuf[NBUF * BUF_FLOATS];

    const int tid = threadIdx.x;
    const int bid = blockIdx.x;
    const int ht = bid & 7;          // h tile (8 rows)
    const int g  = (bid >> 3) & 7;
    const int b  = bid >> 6;
    const int h0 = ht * TH;
    const int wp = tid & 31;         // w-pair lane
    const int hq = tid >> 5;         // 0..3 -> h-pair
    const int ha = h0 + 2 * hq;
    const int wa = 2 * wp;

    unsigned smem_base;
    {
        unsigned long long t;
        asm("cvta.to.shared.u64 %0, %1;" : "=l"(t) : "l"((const void*)sbuf));
        smem_base = (unsigned)t;
    }

    // zero all buffers (OOB/padding slots must stay 0 forever)
    for (int i = tid; i < NBUF * BUF_FLOATS; i += NTHREADS) sbuf[i] = 0.0f;

    // ---- weights: two R2-style packed sets (ha and hb = ha+1), 196 regs total
    // even output wa: P0*(w0,w1)+P1*(w2,w3)+P2*(w4,w5)+P3.lo*w6
    // odd  output   : P0.hi*o0 + P1*(o1,o2)+P2*(o3,o4)+P3*(o5,o6)
    const float* wbase = wt + ((b * 8 + g) * 49) * 4096 + ha * 64 + wa;
    unsigned long long WEa[7][3], WOa[7][3], WEb[7][3], WOb[7][3];
    float WEsa[7], WOsa[7], WEsb[7], WOsb[7];
#pragma unroll
    for (int kh = 0; kh < 7; kh++) {
        float wea[7], woa[7], web[7], wob[7];
#pragma unroll
        for (int kw = 0; kw < 7; kw++) {
            const float* wp2 = wbase + (kh * 7 + kw) * 4096;
            float2 pa = *(const float2*)wp2;          // row ha
            float2 pb = *(const float2*)(wp2 + 64);   // row hb
            wea[kw] = pa.x; woa[kw] = pa.y;
            web[kw] = pb.x; wob[kw] = pb.y;
        }
        WEa[kh][0] = pk2(wea[0], wea[1]); WEa[kh][1] = pk2(wea[2], wea[3]); WEa[kh][2] = pk2(wea[4], wea[5]);
        WEsa[kh] = wea[6];
        WOa[kh][0] = pk2(woa[1], woa[2]); WOa[kh][1] = pk2(woa[3], woa[4]); WOa[kh][2] = pk2(woa[5], woa[6]);
        WOsa[kh] = woa[0];
        WEb[kh][0] = pk2(web[0], web[1]); WEb[kh][1] = pk2(web[2], web[3]); WEb[kh][2] = pk2(web[4], web[5]);
        WEsb[kh] = web[6];
        WOb[kh][0] = pk2(wob[1], wob[2]); WOb[kh][1] = pk2(wob[3], wob[4]); WOb[kh][2] = pk2(wob[5], wob[6]);
        WOsb[kh] = wob[0];
    }

    // ---- cp.async slots, packed: bits[0:10)=smem word, [10:23)=goff+195, [23]=ok
    unsigned enc[8];
#pragma unroll
    for (int k = 0; k < 8; k++) {
        int idx = tid + k * NTHREADS;
        int row = idx / 70;
        int col = idx - row * 70;
        int hh = h0 - 3 + row;
        int ww = col - 3;
        int ok = (idx < TILE_ELEMS) && (hh >= 0) && (hh < 64) && (ww >= 0) && (ww < 64);
        enc[k] = (unsigned)(row * SMW + col) | ((unsigned)(hh * 64 + ww + 195) << 10)
               | ((unsigned)ok << 23);
    }

    const float* xg = x + ((b * 8 + g) * 64) * 4096;
    float* oga = out + ((b * 8 + g) * 64) * 4096 + ha * 64 + wa;

    __syncthreads();   // zeroing done before any cp.async lands

    // ---- prologue: channels 0..3
#pragma unroll
    for (int pre = 0; pre < 4; pre++) {
        unsigned dbase = smem_base + pre * BUF_BYTES;
        const float* xs = xg + pre * 4096;
#pragma unroll
        for (int k = 0; k < 8; k++) {
            unsigned e = enc[k];
            if (e >> 23) cp_async4(dbase + (e & 1023u) * 4u, xs + (((e >> 10) & 8191u) - 195u));
        }
        cp_commit();
    }

    unsigned load_base = smem_base + 4 * BUF_BYTES;   // buffer for channel c+4
    unsigned comp_base = smem_base;                   // buffer for channel c
    const float* xload = xg + 4 * 4096;

#pragma unroll 1
    for (int c = 0; c < 64; c++) {
        if (c < 60) {
#pragma unroll
            for (int k = 0; k < 8; k++) {
                unsigned e = enc[k];
                if (e >> 23) cp_async4(load_base + (e & 1023u) * 4u,
                                       xload + (((e >> 10) & 8191u) - 195u));
            }
        }
        cp_commit();
        cp_wait4();
        __syncthreads();

        // compute 2x2 outputs for channel c
        const float* sb = sbuf + (comp_base - smem_base) / 4 + (2 * hq) * SMW + wa;
        unsigned long long aeA = 0, aoA = 0, aeB = 0, aoB = 0;
        float seA = 0.f, soA = 0.f, seB = 0.f, soB = 0.f;
#pragma unroll
        for (int r = 0; r < 8; r++) {
            const unsigned long long* p = (const unsigned long long*)(sb + r * SMW);
            unsigned long long P0 = p[0];
            unsigned long long P1 = p[1];
            unsigned long long P2 = p[2];
            unsigned long long P3 = p[3];
            if (r < 7) {            // feeds ha with kh = r
                aeA = ffma2(P0, WEa[r][0], aeA);
                aoA = ffma2(P1, WOa[r][0], aoA);
                aeA = ffma2(P1, WEa[r][1], aeA);
                aoA = ffma2(P2, WOa[r][1], aoA);
                aeA = ffma2(P2, WEa[r][2], aeA);
                aoA = ffma2(P3, WOa[r][2], aoA);
                seA = fmaf(f2lo(P3), WEsa[r], seA);
                soA = fmaf(f2hi(P0), WOsa[r], soA);
            }
            if (r > 0) {            // feeds hb with kh = r-1
                aeB = ffma2(P0, WEb[r - 1][0], aeB);
                aoB = ffma2(P1, WOb[r - 1][0], aoB);
                aeB = ffma2(P1, WEb[r - 1][1], aeB);
                aoB = ffma2(P2, WOb[r - 1][1], aoB);
                aeB = ffma2(P2, WEb[r - 1][2], aeB);
                aoB = ffma2(P3, WOb[r - 1][2], aoB);
                seB = fmaf(f2lo(P3), WEsb[r - 1], seB);
                soB = fmaf(f2hi(P0), WOsb[r - 1], soB);
            }
        }
        float* oc = oga + c * 4096;
        *(float2*)oc        = make_float2(f2lo(aeA) + f2hi(aeA) + seA, f2lo(aoA) + f2hi(aoA) + soA);
        *(float2*)(oc + 64) = make_float2(f2lo(aeB) + f2hi(aeB) + seB, f2lo(aoB) + f2hi(aoB) + soB);

        load_base += BUF_BYTES;
        if (load_base >= smem_base + NBUF * BUF_BYTES) load_base -= NBUF * BUF_BYTES;
        comp_base += BUF_BYTES;
        if (comp_base >= smem_base + NBUF * BUF_BYTES) comp_base -= NBUF * BUF_BYTES;
        xload += 4096;
    }
}

extern "C" void kernel_launch(void* const* d_in, const int* in_sizes, int n_in,
                              void* d_out, int out_size) {
    const float* x  = (const float*)d_in[0];
    const float* wt = (const float*)d_in[1];
    if (n_in >= 2 && in_sizes[0] == 8 * 8 * 7 * 7 * 64 * 64) {
        const float* t = x; x = wt; wt = t;
    }
    float* out = (float*)d_out;
    involution_kernel<<<512, NTHREADS>>>(x, wt, out);
}